// round 16
// baseline (speedup 1.0000x reference)
#include <cuda_runtime.h>
#include <cstdint>

#define M_TOTAL 32768
#define E_DIM 2048
#define L_DIM 64
#define H_DIM 128
#define S_LEN 4096

// Scratch (device globals: allocation-free rule)
__device__ float g_q[(size_t)M_TOTAL * H_DIM];
__device__ float g_k[(size_t)M_TOTAL * H_DIM];
__device__ float g_v[(size_t)M_TOTAL * H_DIM];

// Pre-rounded (tf32-rna) weights, same layouts as inputs:
#define WR_DKV 0
#define WR_Q   (2048 * 64)
#define WR_K   (WR_Q + 2048 * 128)
#define WR_V   (WR_K + 64 * 128)
#define WR_TOT (WR_V + 64 * 128)
__device__ float g_wr[WR_TOT];

// ---------------- tf32 / async helpers ----------------

__device__ __forceinline__ void mma_tf32(float* d, const uint32_t* a, const uint32_t* b) {
    asm volatile(
        "mma.sync.aligned.m16n8k8.row.col.f32.tf32.tf32.f32 "
        "{%0,%1,%2,%3}, {%4,%5,%6,%7}, {%8,%9}, {%0,%1,%2,%3};\n"
        : "+f"(d[0]), "+f"(d[1]), "+f"(d[2]), "+f"(d[3])
        : "r"(a[0]), "r"(a[1]), "r"(a[2]), "r"(a[3]), "r"(b[0]), "r"(b[1]));
}

__device__ __forceinline__ uint32_t to_tf32(float x) {
    uint32_t h;
    asm("cvt.rna.tf32.f32 %0, %1;" : "=r"(h) : "f"(x));
    return h;
}

__device__ __forceinline__ void cp16(void* dst, const void* src) {
    uint32_t d = (uint32_t)__cvta_generic_to_shared(dst);
    asm volatile("cp.async.cg.shared.global [%0], [%1], 16;\n" :: "r"(d), "l"(src));
}
#define CP_COMMIT asm volatile("cp.async.commit_group;\n")
#define CP_WAIT0  asm volatile("cp.async.wait_group 0;\n")
#define CP_WAIT1  asm volatile("cp.async.wait_group 1;\n")
#define CP_WAIT2  asm volatile("cp.async.wait_group 2;\n")

// k scale folded into the fused epilogue: 1/sqrt(128) * log2(e)
#define KSCALE_C (0.08838834764831845f * 1.4426950408889634f)

// ---------------- weight pre-rounding (once per call, ~5us) ----------------

__global__ void prep_w(const float* __restrict__ w_dkv, const float* __restrict__ w_q,
                       const float* __restrict__ w_k, const float* __restrict__ w_v) {
    int i = blockIdx.x * 256 + threadIdx.x;
    float v;
    if (i < WR_Q)       v = w_dkv[i];
    else if (i < WR_K)  v = w_q[i - WR_Q];
    else if (i < WR_V)  v = w_k[i - WR_K];
    else                v = w_v[i - WR_V];
    g_wr[i] = __uint_as_float(to_tf32(v));
}

// ---------------- fused GEMM1 + k/v decompress ----------------
// Main loop: [latent(64) | q(128)] = x @ [w_dkv|w_q] (1xTF32, 3-stage cp.async).
// q stored rna-rounded (attention reads raw bits). Epilogue: k = latent@w_k
// (KSCALE, rna), v = latent@w_v (rna) in-CTA. BM=64, 256 thr, 8 warps 2m x 4n.

constexpr int G_BN = 192;
constexpr int G_KT = 32;
constexpr int G_ASTR = 36;
constexpr int G_BSTR = G_BN + 8;              // 200
constexpr int G_ASZ = 64 * G_ASTR;            // 2304
constexpr int G_BSZ = G_KT * G_BSTR;          // 6400
constexpr int G_BUF = G_ASZ + G_BSZ;          // 8704 floats
constexpr int G_SMEM = 3 * G_BUF * 4;         // 104448 bytes
constexpr int WSTR = 264;
constexpr int EP_WS = 0;
constexpr int EP_LS = 64 * WSTR;
constexpr int LSTR = 68;
static_assert(EP_LS + 64 * LSTR <= 3 * G_BUF, "epilogue overlay fits");

__global__ void __launch_bounds__(256, 2) gemm1_fused(
    const float* __restrict__ A,
    const float* __restrict__ wr,
    float* __restrict__ latent, float* __restrict__ qout,
    float* __restrict__ kout, float* __restrict__ vout)
{
    extern __shared__ float sh[];

    const int tid = threadIdx.x;
    const int warp = tid >> 5, lane = tid & 31;
    const int wm = warp >> 2;
    const int wn = warp & 3;
    const int lr = lane >> 2, lc = lane & 3;
    const int m0 = blockIdx.x * 64;

    const int arow = tid >> 2;
    const int ac4 = (tid & 3) * 4;

    const float* B1 = wr + WR_DKV;
    const float* B2 = wr + WR_Q;

    float acc[2][6][4];
#pragma unroll
    for (int mt = 0; mt < 2; mt++)
#pragma unroll
        for (int nt = 0; nt < 6; nt++)
#pragma unroll
            for (int j = 0; j < 4; j++) acc[mt][nt][j] = 0.f;

    const int nk = E_DIM / G_KT;

    auto stage = [&](int kt) {
        float* As = sh + (kt % 3) * G_BUF;
        float* Bs = As + G_ASZ;
        int kb = kt * G_KT;
        cp16(&As[arow * G_ASTR + ac4],      A + (size_t)(m0 + arow) * E_DIM + kb + ac4);
        cp16(&As[arow * G_ASTR + ac4 + 16], A + (size_t)(m0 + arow) * E_DIM + kb + ac4 + 16);
        constexpr int NB = (G_KT * G_BN / 4) / 256;  // 6
#pragma unroll
        for (int it = 0; it < NB; it++) {
            int i = it * 256 + tid;
            int brow = i / (G_BN / 4);
            int bc4 = (i % (G_BN / 4)) * 4;
            const float* src = (bc4 < 64) ? (B1 + (size_t)(kb + brow) * L_DIM + bc4)
                                          : (B2 + (size_t)(kb + brow) * H_DIM + (bc4 - 64));
            cp16(&Bs[brow * G_BSTR + bc4], src);
        }
        CP_COMMIT;
    };

    stage(0);
    stage(1);

    for (int kt = 0; kt < nk; kt++) {
        if (kt + 2 < nk) { stage(kt + 2); CP_WAIT2; }
        else if (kt + 1 < nk) CP_WAIT1;
        else CP_WAIT0;
        __syncthreads();

        const float* As = sh + (kt % 3) * G_BUF;
        const float* Bs = As + G_ASZ;

#pragma unroll
        for (int ks = 0; ks < 4; ks++) {
            uint32_t ah[2][4];
#pragma unroll
            for (int mt = 0; mt < 2; mt++) {
                int rb = wm * 32 + mt * 16;
                ah[mt][0] = to_tf32(As[(rb + lr) * G_ASTR + ks * 8 + lc]);
                ah[mt][1] = to_tf32(As[(rb + lr + 8) * G_ASTR + ks * 8 + lc]);
                ah[mt][2] = to_tf32(As[(rb + lr) * G_ASTR + ks * 8 + lc + 4]);
                ah[mt][3] = to_tf32(As[(rb + lr + 8) * G_ASTR + ks * 8 + lc + 4]);
            }
#pragma unroll
            for (int nt = 0; nt < 6; nt++) {
                int c0 = wn * 48 + nt * 8 + lr;
                uint32_t bh[2];
                bh[0] = __float_as_uint(Bs[(ks * 8 + lc) * G_BSTR + c0]);
                bh[1] = __float_as_uint(Bs[(ks * 8 + lc + 4) * G_BSTR + c0]);
#pragma unroll
                for (int mt = 0; mt < 2; mt++)
                    mma_tf32(acc[mt][nt], ah[mt], bh);
            }
        }
        __syncthreads();
    }

    // ---- epilogue: stage w_k|w_v into dead pipeline smem (overlapped) ----
    {
        float* Ws = sh + EP_WS;
#pragma unroll
        for (int it = 0; it < 16; it++) {
            int i = it * 256 + tid;
            int row = i >> 6;
            int c4 = (i & 63) * 4;
            const float* src = (c4 < 128) ? (wr + WR_K + (size_t)row * H_DIM + c4)
                                          : (wr + WR_V + (size_t)row * H_DIM + (c4 - 128));
            cp16(&Ws[row * WSTR + c4], src);
        }
        CP_COMMIT;
    }

    // ---- store latent (fp32, d_out + smem) and q (rna-rounded, gmem) ----
    {
        float* Ls = sh + EP_LS;
#pragma unroll
        for (int mt = 0; mt < 2; mt++) {
            int rloc = wm * 32 + mt * 16 + lr;
            int r0 = m0 + rloc;
#pragma unroll
            for (int nt = 0; nt < 6; nt++) {
                int gc = wn * 48 + nt * 8 + lc * 2;
                if (gc < 64) {
                    float2 v01 = make_float2(acc[mt][nt][0], acc[mt][nt][1]);
                    float2 v23 = make_float2(acc[mt][nt][2], acc[mt][nt][3]);
                    *(float2*)(latent + (size_t)r0 * L_DIM + gc)       = v01;
                    *(float2*)(latent + (size_t)(r0 + 8) * L_DIM + gc) = v23;
                    *(float2*)&Ls[rloc * LSTR + gc]       = v01;
                    *(float2*)&Ls[(rloc + 8) * LSTR + gc] = v23;
                } else {
                    float2 v01 = make_float2(__uint_as_float(to_tf32(acc[mt][nt][0])),
                                             __uint_as_float(to_tf32(acc[mt][nt][1])));
                    float2 v23 = make_float2(__uint_as_float(to_tf32(acc[mt][nt][2])),
                                             __uint_as_float(to_tf32(acc[mt][nt][3])));
                    *(float2*)(qout + (size_t)r0 * H_DIM + gc - 64)       = v01;
                    *(float2*)(qout + (size_t)(r0 + 8) * H_DIM + gc - 64) = v23;
                }
            }
        }
    }
    CP_WAIT0;
    __syncthreads();

    // ---- k|v = latent @ [w_k|w_v] : warp = 32 rows (2mt) x 64 cols (8nt) ----
    {
        const float* Ws = sh + EP_WS;
        const float* Ls = sh + EP_LS;
        float acc2[2][8][4];
#pragma unroll
        for (int mt = 0; mt < 2; mt++)
#pragma unroll
            for (int nt = 0; nt < 8; nt++)
#pragma unroll
                for (int j = 0; j < 4; j++) acc2[mt][nt][j] = 0.f;

#pragma unroll
        for (int ks = 0; ks < 8; ks++) {
            uint32_t ah[2][4];
#pragma unroll
            for (int mt = 0; mt < 2; mt++) {
                int rb = wm * 32 + mt * 16;
                ah[mt][0] = to_tf32(Ls[(rb + lr) * LSTR + ks * 8 + lc]);
                ah[mt][1] = to_tf32(Ls[(rb + lr + 8) * LSTR + ks * 8 + lc]);
                ah[mt][2] = to_tf32(Ls[(rb + lr) * LSTR + ks * 8 + lc + 4]);
                ah[mt][3] = to_tf32(Ls[(rb + lr + 8) * LSTR + ks * 8 + lc + 4]);
            }
#pragma unroll
            for (int nt = 0; nt < 8; nt++) {
                int c0 = wn * 64 + nt * 8 + lr;
                uint32_t bh[2];
                bh[0] = __float_as_uint(Ws[(ks * 8 + lc) * WSTR + c0]);
                bh[1] = __float_as_uint(Ws[(ks * 8 + lc + 4) * WSTR + c0]);
#pragma unroll
                for (int mt = 0; mt < 2; mt++)
                    mma_tf32(acc2[mt][nt], ah[mt], bh);
            }
        }

#pragma unroll
        for (int mt = 0; mt < 2; mt++) {
            int r0 = m0 + wm * 32 + mt * 16 + lr;
#pragma unroll
            for (int nt = 0; nt < 8; nt++) {
                int gc = wn * 64 + nt * 8 + lc * 2;
                float* dst;
                int col;
                float cs;
                if (gc < 128) { dst = kout; col = gc;       cs = KSCALE_C; }
                else          { dst = vout; col = gc - 128; cs = 1.f; }
                float o0 = __uint_as_float(to_tf32(acc2[mt][nt][0] * cs));
                float o1 = __uint_as_float(to_tf32(acc2[mt][nt][1] * cs));
                float o2 = __uint_as_float(to_tf32(acc2[mt][nt][2] * cs));
                float o3 = __uint_as_float(to_tf32(acc2[mt][nt][3] * cs));
                *(float2*)(dst + (size_t)r0 * H_DIM + col)       = make_float2(o0, o1);
                *(float2*)(dst + (size_t)(r0 + 8) * H_DIM + col) = make_float2(o2, o3);
            }
        }
    }
}

// ---------------- Flash attention (causal), 256 threads, 16 warps/SM ----------------
// BLOCK_M=64, 8 warps = (wr: 4 x 16-row group) x (wn: 32-kv half QK / 64-head
// half PV). All of q, k, v pre-rounded tf32-rna in gmem -> zero cvt in loops.
// q read from smem Q tile per k-step (no q register state -> regs ~110, 2 CTAs
// of 256 thr/SM = 16 warps/SM). P aliases Ks. Cross-warp softmax over wn pairs
// via separate Xm/Xr exchange buffers. exp2-domain softmax (scale in k).

constexpr int AKS = 132;
constexpr int AVS = 136;
constexpr int APS = 68;
constexpr int VOFF  = 64 * AKS;             // 8448
constexpr int QOFF  = VOFF + 64 * AVS;      // 17152
constexpr int XMOFF = QOFF + 64 * 132;      // 25600
constexpr int XROFF = XMOFF + 128;          // 25728
constexpr int ATTN_SMEM_BYTES = (XROFF + 128) * 4;   // 103424

__global__ void __launch_bounds__(256, 2) attn_kernel(
    const float* __restrict__ q, const float* __restrict__ k,
    const float* __restrict__ v, float* __restrict__ out)
{
    extern __shared__ float sm[];
    float* Ks = sm;                 // K tile; aliased as P (stride APS) after QK
    float* Vs = sm + VOFF;
    float* Qs = sm + QOFF;
    float* Xm = sm + XMOFF;
    float* Xr = sm + XROFF;

    const int idx = blockIdx.x;
    const int b = idx & 7;
    const int qb = 63 - (idx >> 3);         // longest first
    const int tid = threadIdx.x;
    const int warp = tid >> 5, lane = tid & 31;
    const int lr = lane >> 2, lc = lane & 3;
    const int wr = warp >> 1;               // 16-row group (0..3)
    const int wn = warp & 1;                // kv half (QK) / head half (PV)

    const float* qB = q + (size_t)b * S_LEN * H_DIM;
    const float* kB = k + (size_t)b * S_LEN * H_DIM;
    const float* vB = v + (size_t)b * S_LEN * H_DIM;

    const int srow = tid >> 2;              // 0..63
    const int scb = (tid & 3) * 32;

    // Stage Q tile (64 x 128) once; q already tf32-rna from gemm1
#pragma unroll
    for (int i = 0; i < 8; i++)
        cp16(&Qs[srow * 132 + scb + i * 4],
             qB + (size_t)(qb * 64 + srow) * H_DIM + scb + i * 4);
    CP_COMMIT;

    float acc[8][4];
#pragma unroll
    for (int nt = 0; nt < 8; nt++)
#pragma unroll
        for (int j = 0; j < 4; j++) acc[nt][j] = 0.f;
    float mrow[2] = {-INFINITY, -INFINITY};
    float lrow[2] = {0.f, 0.f};

    const int qrow = wr * 16 + lr;

    for (int kv = 0; kv <= qb; kv++) {
        __syncthreads();  // (1) Ks(P)/Vs fully consumed

        // stage K,V tile (64 x 128 each)
#pragma unroll
        for (int i = 0; i < 8; i++)
            cp16(&Ks[srow * AKS + scb + i * 4],
                 kB + (size_t)(kv * 64 + srow) * H_DIM + scb + i * 4);
#pragma unroll
        for (int i = 0; i < 8; i++)
            cp16(&Vs[srow * AVS + scb + i * 4],
                 vB + (size_t)(kv * 64 + srow) * H_DIM + scb + i * 4);
        CP_COMMIT;
        CP_WAIT0;
        __syncthreads();  // (2) tiles ready (Q included on first iteration)

        // ---- S = q @ k^T : 16 rows x 32 kv cols per warp, 1xTF32, no cvt ----
        float sc[4][4];
#pragma unroll
        for (int nt = 0; nt < 4; nt++)
#pragma unroll
            for (int j = 0; j < 4; j++) sc[nt][j] = 0.f;

#pragma unroll
        for (int ks = 0; ks < 16; ks++) {
            uint32_t qf[4];
            qf[0] = __float_as_uint(Qs[qrow * 132 + ks * 8 + lc]);
            qf[1] = __float_as_uint(Qs[(qrow + 8) * 132 + ks * 8 + lc]);
            qf[2] = __float_as_uint(Qs[qrow * 132 + ks * 8 + lc + 4]);
            qf[3] = __float_as_uint(Qs[(qrow + 8) * 132 + ks * 8 + lc + 4]);
#pragma unroll
            for (int nt = 0; nt < 4; nt++) {
                int kr = wn * 32 + nt * 8 + lr;
                uint32_t bh[2];
                bh[0] = __float_as_uint(Ks[kr * AKS + ks * 8 + lc]);
                bh[1] = __float_as_uint(Ks[kr * AKS + ks * 8 + lc + 4]);
                mma_tf32(sc[nt], qf, bh);
            }
        }

        // Diagonal-block causal mask (tile-local coords)
        if (kv == qb) {
#pragma unroll
            for (int nt = 0; nt < 4; nt++)
#pragma unroll
                for (int j = 0; j < 4; j++) {
                    int col = wn * 32 + nt * 8 + lc * 2 + (j & 1);
                    int row = wr * 16 + lr + (j >> 1) * 8;
                    if (col > row) sc[nt][j] = -INFINITY;
                }
        }

        // ---- online softmax (exp2 domain, cross-warp over wn pair) ----
        float mnew[2] = {-INFINITY, -INFINITY};
#pragma unroll
        for (int nt = 0; nt < 4; nt++)
#pragma unroll
            for (int j = 0; j < 4; j++) mnew[j >> 1] = fmaxf(mnew[j >> 1], sc[nt][j]);
#pragma unroll
        for (int off = 1; off < 4; off <<= 1) {
            mnew[0] = fmaxf(mnew[0], __shfl_xor_sync(0xffffffffu, mnew[0], off));
            mnew[1] = fmaxf(mnew[1], __shfl_xor_sync(0xffffffffu, mnew[1], off));
        }
        if (lc == 0) {
#pragma unroll
            for (int h = 0; h < 2; h++)
                Xm[((wr * 2 + wn) * 2 + h) * 8 + lr] = mnew[h];
        }
        __syncthreads();  // (3) m-exchange; also: all QK reads of Ks done

        float alpha[2];
#pragma unroll
        for (int h = 0; h < 2; h++) {
            float mo = Xm[((wr * 2 + (1 - wn)) * 2 + h) * 8 + lr];
            float mt_ = fmaxf(fmaxf(mrow[h], mnew[h]), mo);
            alpha[h] = exp2f(mrow[h] - mt_);
            mrow[h] = mt_;
        }

        float rs[2] = {0.f, 0.f};
#pragma unroll
        for (int nt = 0; nt < 4; nt++)
#pragma unroll
            for (int j = 0; j < 4; j++) {
                float p = exp2f(sc[nt][j] - mrow[j >> 1]);
                sc[nt][j] = p;
                rs[j >> 1] += p;
            }
#pragma unroll
        for (int off = 1; off < 4; off <<= 1) {
            rs[0] += __shfl_xor_sync(0xffffffffu, rs[0], off);
            rs[1] += __shfl_xor_sync(0xffffffffu, rs[1], off);
        }

        // write P (rna) into dead Ks region; write rs partials
#pragma unroll
        for (int nt = 0; nt < 4; nt++)
#pragma unroll
            for (int j = 0; j < 4; j++) {
                int row = wr * 16 + lr + (j >> 1) * 8;
                int col = wn * 32 + nt * 8 + lc * 2 + (j & 1);
                Ks[row * APS + col] = __uint_as_float(to_tf32(sc[nt][j]));
            }
        if (lc == 0) {
#pragma unroll
            for (int h = 0; h < 2; h++)
                Xr[((wr * 2 + wn) * 2 + h) * 8 + lr] = rs[h];
        }
        __syncthreads();  // (4) P + rs ready

#pragma unroll
        for (int h = 0; h < 2; h++) {
            float ro = Xr[((wr * 2 + (1 - wn)) * 2 + h) * 8 + lr];
            lrow[h] = lrow[h] * alpha[h] + rs[h] + ro;
        }

#pragma unroll
        for (int nt = 0; nt < 8; nt++) {
            acc[nt][0] *= alpha[0]; acc[nt][1] *= alpha[0];
            acc[nt][2] *= alpha[1]; acc[nt][3] *= alpha[1];
        }

        // ---- O += P @ V : 16 rows x 64 head cols per warp, 1xTF32 ----
#pragma unroll
        for (int ks2 = 0; ks2 < 8; ks2++) {
            uint32_t pa[4];
            pa[0] = __float_as_uint(Ks[(wr * 16 + lr) * APS + ks2 * 8 + lc]);
            pa[1] = __float_as_uint(Ks[(wr * 16 + lr + 8) * APS + ks2 * 8 + lc]);
            pa[2] = __float_as_uint(Ks[(wr * 16 + lr) * APS + ks2 * 8 + lc + 4]);
            pa[3] = __float_as_uint(Ks[(wr * 16 + lr + 8) * APS + ks2 * 8 + lc + 4]);
#pragma unroll
            for (int nt2 = 0; nt2 < 8; nt2++) {
                int vc = wn * 64 + nt2 * 8 + lr;
                uint32_t vb[2];
                vb[0] = __float_as_uint(Vs[(ks2 * 8 + lc) * AVS + vc]);
                vb[1] = __float_as_uint(Vs[(ks2 * 8 + lc + 4) * AVS + vc]);
                mma_tf32(acc[nt2], pa, vb);
            }
        }
    }

    // Epilogue
    float inv0 = 1.f / lrow[0];
    float inv1 = 1.f / lrow[1];
    size_t rowg = (size_t)b * S_LEN + qb * 64 + wr * 16 + lr;
#pragma unroll
    for (int nt2 = 0; nt2 < 8; nt2++) {
        int col = wn * 64 + nt2 * 8 + lc * 2;
        *(float2*)(out + rowg * H_DIM + col) =
            make_float2(acc[nt2][0] * inv0, acc[nt2][1] * inv0);
        *(float2*)(out + (rowg + 8) * H_DIM + col) =
            make_float2(acc[nt2][2] * inv1, acc[nt2][3] * inv1);
    }
}

// ---------------- launch ----------------

extern "C" void kernel_launch(void* const* d_in, const int* in_sizes, int n_in,
                              void* d_out, int out_size) {
    const float* x     = (const float*)d_in[0];
    const float* w_dkv = (const float*)d_in[1];
    const float* w_k   = (const float*)d_in[2];
    const float* w_v   = (const float*)d_in[3];
    const float* w_q   = (const float*)d_in[4];

    float* out = (float*)d_out;                          // [B,S,HEAD]
    float* latent = out + (size_t)M_TOTAL * H_DIM;       // [B,S,LATENT]

    float *qp, *kp, *vp, *wr;
    cudaGetSymbolAddress((void**)&qp, g_q);
    cudaGetSymbolAddress((void**)&kp, g_k);
    cudaGetSymbolAddress((void**)&vp, g_v);
    cudaGetSymbolAddress((void**)&wr, g_wr);

    static bool attrs_set = false;
    if (!attrs_set) {
        cudaFuncSetAttribute(gemm1_fused,
                             cudaFuncAttributeMaxDynamicSharedMemorySize, G_SMEM);
        cudaFuncSetAttribute(attn_kernel,
                             cudaFuncAttributeMaxDynamicSharedMemorySize, ATTN_SMEM_BYTES);
        attrs_set = true;
    }

    // 0) pre-round all weights to tf32-rna (unbiased)
    prep_w<<<WR_TOT / 256, 256>>>(w_dkv, w_q, w_k, w_v);

    // 1) fused: latent -> d_out; q (rna), k (scaled, rna), v (rna) -> scratch
    gemm1_fused<<<M_TOTAL / 64, 256, G_SMEM>>>(x, wr, latent, qp, kp, vp);

    // 2) causal flash attention (512 CTAs x 256 thr, 2/SM = 16 warps/SM)
    attn_kernel<<<512, 256, ATTN_SMEM_BYTES>>>(qp, kp, vp, out);
}

// round 17
// speedup vs baseline: 1.5940x; 1.5940x over previous
#include <cuda_runtime.h>
#include <cstdint>

#define M_TOTAL 32768
#define E_DIM 2048
#define L_DIM 64
#define H_DIM 128
#define S_LEN 4096

// Scratch (device globals: allocation-free rule)
__device__ float g_q[(size_t)M_TOTAL * H_DIM];
__device__ float g_k[(size_t)M_TOTAL * H_DIM];
__device__ float g_v[(size_t)M_TOTAL * H_DIM];

// Pre-rounded (tf32-rna) weights, same layouts as inputs:
#define WR_DKV 0
#define WR_Q   (2048 * 64)
#define WR_K   (WR_Q + 2048 * 128)
#define WR_V   (WR_K + 64 * 128)
#define WR_TOT (WR_V + 64 * 128)
__device__ float g_wr[WR_TOT];

// ---------------- tf32 / async helpers ----------------

__device__ __forceinline__ void mma_tf32(float* d, const uint32_t* a, const uint32_t* b) {
    asm volatile(
        "mma.sync.aligned.m16n8k8.row.col.f32.tf32.tf32.f32 "
        "{%0,%1,%2,%3}, {%4,%5,%6,%7}, {%8,%9}, {%0,%1,%2,%3};\n"
        : "+f"(d[0]), "+f"(d[1]), "+f"(d[2]), "+f"(d[3])
        : "r"(a[0]), "r"(a[1]), "r"(a[2]), "r"(a[3]), "r"(b[0]), "r"(b[1]));
}

__device__ __forceinline__ uint32_t to_tf32(float x) {
    uint32_t h;
    asm("cvt.rna.tf32.f32 %0, %1;" : "=r"(h) : "f"(x));
    return h;
}

__device__ __forceinline__ void cp16(void* dst, const void* src) {
    uint32_t d = (uint32_t)__cvta_generic_to_shared(dst);
    asm volatile("cp.async.cg.shared.global [%0], [%1], 16;\n" :: "r"(d), "l"(src));
}
#define CP_COMMIT asm volatile("cp.async.commit_group;\n")
#define CP_WAIT0  asm volatile("cp.async.wait_group 0;\n")
#define CP_WAIT1  asm volatile("cp.async.wait_group 1;\n")

// k scale folded into the fused epilogue: 1/sqrt(128) * log2(e)
#define KSCALE_C (0.08838834764831845f * 1.4426950408889634f)

// ---------------- weight pre-rounding (once per call, ~5us) ----------------

__global__ void prep_w(const float* __restrict__ w_dkv, const float* __restrict__ w_q,
                       const float* __restrict__ w_k, const float* __restrict__ w_v) {
    int i = blockIdx.x * 256 + threadIdx.x;
    float v;
    if (i < WR_Q)       v = w_dkv[i];
    else if (i < WR_K)  v = w_q[i - WR_Q];
    else if (i < WR_V)  v = w_k[i - WR_K];
    else                v = w_v[i - WR_V];
    g_wr[i] = __uint_as_float(to_tf32(v));
}

// ---------------- fused GEMM1 + k/v decompress, 2-stage / 2 CTAs-per-SM ----------
// Main loop: [latent(64) | q(128)] = x @ [w_dkv|w_q] (1xTF32, 2-stage cp.async,
// cross-CTA hiding via 2 resident CTAs). q stored rna-rounded.
// Epilogue: k = latent@w_k (KSCALE, rna), v = latent@w_v (rna) in-CTA.
// BM=64, 256 thr, 8 warps 2m x 4n.

constexpr int G_BN = 192;
constexpr int G_KT = 32;
constexpr int G_ASTR = 36;
constexpr int G_BSTR = G_BN + 8;              // 200
constexpr int G_ASZ = 64 * G_ASTR;            // 2304
constexpr int G_BSZ = G_KT * G_BSTR;          // 6400
constexpr int G_BUF = G_ASZ + G_BSZ;          // 8704 floats
// epilogue overlay region (re-uses the whole smem block after the main loop):
constexpr int WSTR = 264;
constexpr int EP_WS = 0;                      // Ws: 64 x 264 = 16896 floats
constexpr int EP_LS = 64 * WSTR;              // Ls: 64 x 68  = 4352 floats
constexpr int LSTR = 68;
constexpr int G_FLOATS = (EP_LS + 64 * LSTR) > (2 * G_BUF) ? (EP_LS + 64 * LSTR)
                                                           : (2 * G_BUF);
constexpr int G_SMEM = G_FLOATS * 4;          // 84992 bytes -> 2 CTAs/SM

__global__ void __launch_bounds__(256, 2) gemm1_fused(
    const float* __restrict__ A,
    const float* __restrict__ wr,
    float* __restrict__ latent, float* __restrict__ qout,
    float* __restrict__ kout, float* __restrict__ vout)
{
    extern __shared__ float sh[];

    const int tid = threadIdx.x;
    const int warp = tid >> 5, lane = tid & 31;
    const int wm = warp >> 2;
    const int wn = warp & 3;
    const int lr = lane >> 2, lc = lane & 3;
    const int m0 = blockIdx.x * 64;

    const int arow = tid >> 2;
    const int ac4 = (tid & 3) * 4;

    const float* B1 = wr + WR_DKV;
    const float* B2 = wr + WR_Q;

    float acc[2][6][4];
#pragma unroll
    for (int mt = 0; mt < 2; mt++)
#pragma unroll
        for (int nt = 0; nt < 6; nt++)
#pragma unroll
            for (int j = 0; j < 4; j++) acc[mt][nt][j] = 0.f;

    const int nk = E_DIM / G_KT;

    auto stage = [&](int kt) {
        float* As = sh + (kt & 1) * G_BUF;
        float* Bs = As + G_ASZ;
        int kb = kt * G_KT;
        cp16(&As[arow * G_ASTR + ac4],      A + (size_t)(m0 + arow) * E_DIM + kb + ac4);
        cp16(&As[arow * G_ASTR + ac4 + 16], A + (size_t)(m0 + arow) * E_DIM + kb + ac4 + 16);
        constexpr int NB = (G_KT * G_BN / 4) / 256;  // 6
#pragma unroll
        for (int it = 0; it < NB; it++) {
            int i = it * 256 + tid;
            int brow = i / (G_BN / 4);
            int bc4 = (i % (G_BN / 4)) * 4;
            const float* src = (bc4 < 64) ? (B1 + (size_t)(kb + brow) * L_DIM + bc4)
                                          : (B2 + (size_t)(kb + brow) * H_DIM + (bc4 - 64));
            cp16(&Bs[brow * G_BSTR + bc4], src);
        }
        CP_COMMIT;
    };

    stage(0);

    for (int kt = 0; kt < nk; kt++) {
        if (kt + 1 < nk) { stage(kt + 1); CP_WAIT1; }
        else CP_WAIT0;
        __syncthreads();

        const float* As = sh + (kt & 1) * G_BUF;
        const float* Bs = As + G_ASZ;

#pragma unroll
        for (int ks = 0; ks < 4; ks++) {
            uint32_t ah[2][4];
#pragma unroll
            for (int mt = 0; mt < 2; mt++) {
                int rb = wm * 32 + mt * 16;
                ah[mt][0] = to_tf32(As[(rb + lr) * G_ASTR + ks * 8 + lc]);
                ah[mt][1] = to_tf32(As[(rb + lr + 8) * G_ASTR + ks * 8 + lc]);
                ah[mt][2] = to_tf32(As[(rb + lr) * G_ASTR + ks * 8 + lc + 4]);
                ah[mt][3] = to_tf32(As[(rb + lr + 8) * G_ASTR + ks * 8 + lc + 4]);
            }
#pragma unroll
            for (int nt = 0; nt < 6; nt++) {
                int c0 = wn * 48 + nt * 8 + lr;
                uint32_t bh[2];
                bh[0] = __float_as_uint(Bs[(ks * 8 + lc) * G_BSTR + c0]);
                bh[1] = __float_as_uint(Bs[(ks * 8 + lc + 4) * G_BSTR + c0]);
#pragma unroll
                for (int mt = 0; mt < 2; mt++)
                    mma_tf32(acc[mt][nt], ah[mt], bh);
            }
        }
        __syncthreads();
    }

    // ---- epilogue: stage w_k|w_v into the (now dead) pipeline smem ----
    {
        float* Ws = sh + EP_WS;
#pragma unroll
        for (int it = 0; it < 16; it++) {
            int i = it * 256 + tid;
            int row = i >> 6;
            int c4 = (i & 63) * 4;
            const float* src = (c4 < 128) ? (wr + WR_K + (size_t)row * H_DIM + c4)
                                          : (wr + WR_V + (size_t)row * H_DIM + (c4 - 128));
            cp16(&Ws[row * WSTR + c4], src);
        }
        CP_COMMIT;
    }

    // ---- store latent (fp32, d_out + smem) and q (rna-rounded, gmem) ----
    {
        float* Ls = sh + EP_LS;
#pragma unroll
        for (int mt = 0; mt < 2; mt++) {
            int rloc = wm * 32 + mt * 16 + lr;
            int r0 = m0 + rloc;
#pragma unroll
            for (int nt = 0; nt < 6; nt++) {
                int gc = wn * 48 + nt * 8 + lc * 2;
                if (gc < 64) {
                    float2 v01 = make_float2(acc[mt][nt][0], acc[mt][nt][1]);
                    float2 v23 = make_float2(acc[mt][nt][2], acc[mt][nt][3]);
                    *(float2*)(latent + (size_t)r0 * L_DIM + gc)       = v01;
                    *(float2*)(latent + (size_t)(r0 + 8) * L_DIM + gc) = v23;
                    *(float2*)&Ls[rloc * LSTR + gc]       = v01;
                    *(float2*)&Ls[(rloc + 8) * LSTR + gc] = v23;
                } else {
                    float2 v01 = make_float2(__uint_as_float(to_tf32(acc[mt][nt][0])),
                                             __uint_as_float(to_tf32(acc[mt][nt][1])));
                    float2 v23 = make_float2(__uint_as_float(to_tf32(acc[mt][nt][2])),
                                             __uint_as_float(to_tf32(acc[mt][nt][3])));
                    *(float2*)(qout + (size_t)r0 * H_DIM + gc - 64)       = v01;
                    *(float2*)(qout + (size_t)(r0 + 8) * H_DIM + gc - 64) = v23;
                }
            }
        }
    }
    CP_WAIT0;
    __syncthreads();

    // ---- k|v = latent @ [w_k|w_v] : warp = 32 rows (2mt) x 64 cols (8nt) ----
    {
        const float* Ws = sh + EP_WS;
        const float* Ls = sh + EP_LS;
        float acc2[2][8][4];
#pragma unroll
        for (int mt = 0; mt < 2; mt++)
#pragma unroll
            for (int nt = 0; nt < 8; nt++)
#pragma unroll
                for (int j = 0; j < 4; j++) acc2[mt][nt][j] = 0.f;

#pragma unroll
        for (int ks = 0; ks < 8; ks++) {
            uint32_t ah[2][4];
#pragma unroll
            for (int mt = 0; mt < 2; mt++) {
                int rb = wm * 32 + mt * 16;
                ah[mt][0] = to_tf32(Ls[(rb + lr) * LSTR + ks * 8 + lc]);
                ah[mt][1] = to_tf32(Ls[(rb + lr + 8) * LSTR + ks * 8 + lc]);
                ah[mt][2] = to_tf32(Ls[(rb + lr) * LSTR + ks * 8 + lc + 4]);
                ah[mt][3] = to_tf32(Ls[(rb + lr + 8) * LSTR + ks * 8 + lc + 4]);
            }
#pragma unroll
            for (int nt = 0; nt < 8; nt++) {
                int c0 = wn * 64 + nt * 8 + lr;
                uint32_t bh[2];
                bh[0] = __float_as_uint(Ws[(ks * 8 + lc) * WSTR + c0]);
                bh[1] = __float_as_uint(Ws[(ks * 8 + lc + 4) * WSTR + c0]);
#pragma unroll
                for (int mt = 0; mt < 2; mt++)
                    mma_tf32(acc2[mt][nt], ah[mt], bh);
            }
        }

#pragma unroll
        for (int mt = 0; mt < 2; mt++) {
            int r0 = m0 + wm * 32 + mt * 16 + lr;
#pragma unroll
            for (int nt = 0; nt < 8; nt++) {
                int gc = wn * 64 + nt * 8 + lc * 2;
                float* dst;
                int col;
                float cs;
                if (gc < 128) { dst = kout; col = gc;       cs = KSCALE_C; }
                else          { dst = vout; col = gc - 128; cs = 1.f; }
                float o0 = __uint_as_float(to_tf32(acc2[mt][nt][0] * cs));
                float o1 = __uint_as_float(to_tf32(acc2[mt][nt][1] * cs));
                float o2 = __uint_as_float(to_tf32(acc2[mt][nt][2] * cs));
                float o3 = __uint_as_float(to_tf32(acc2[mt][nt][3] * cs));
                *(float2*)(dst + (size_t)r0 * H_DIM + col)       = make_float2(o0, o1);
                *(float2*)(dst + (size_t)(r0 + 8) * H_DIM + col) = make_float2(o2, o3);
            }
        }
    }
}

// ---------------- Flash attention (causal), R15 (pipelined K/V, frozen) ----------
// 4 warps x 16 rows, each warp spans all 64 kv cols (QK) and 128 head cols (PV);
// warp-local softmax, private P. K(t+1) issued after QK(t); V(t+1) after PV(t).
// q/k/v all tf32-rna from gemm1 -> zero cvt in loops; exp2 softmax (scale in k).

constexpr int AKS = 132;
constexpr int AVS = 136;
constexpr int APS = 68;
constexpr int VOFF = 64 * AKS;              // 8448
constexpr int POFF = VOFF + 64 * AVS;       // 17152
constexpr int ATTN_SMEM_BYTES = (POFF + 64 * APS) * 4;   // 86016

__global__ void __launch_bounds__(128, 2) attn_kernel(
    const float* __restrict__ q, const float* __restrict__ k,
    const float* __restrict__ v, float* __restrict__ out)
{
    extern __shared__ float sm[];
    float* Ks = sm;
    float* Vs = sm + VOFF;
    float* Ps = sm + POFF;

    const int idx = blockIdx.x;
    const int b = idx & 7;
    const int qb = 63 - (idx >> 3);         // longest first
    const int tid = threadIdx.x;
    const int warp = tid >> 5, lane = tid & 31;
    const int lr = lane >> 2, lc = lane & 3;

    const float* qB = q + (size_t)b * S_LEN * H_DIM;
    const float* kB = k + (size_t)b * S_LEN * H_DIM;
    const float* vB = v + (size_t)b * S_LEN * H_DIM;

    const int qrow0 = qb * 64 + warp * 16 + lr;

    const int row64 = tid >> 5;
    const int c4 = (tid & 31) * 4;

    auto loadK = [&](int t) {
#pragma unroll
        for (int rnd = 0; rnd < 16; rnd++) {
            int row = row64 + rnd * 4;
            cp16(&Ks[row * AKS + c4], kB + (size_t)(t * 64 + row) * H_DIM + c4);
        }
        CP_COMMIT;
    };
    auto loadV = [&](int t) {
#pragma unroll
        for (int rnd = 0; rnd < 16; rnd++) {
            int row = row64 + rnd * 4;
            cp16(&Vs[row * AVS + c4], vB + (size_t)(t * 64 + row) * H_DIM + c4);
        }
        CP_COMMIT;
    };

    // q fragments in registers; q already tf32-rna from gemm1 (raw bits, no cvt)
    uint32_t qr[64];
#pragma unroll
    for (int ks = 0; ks < 16; ks++) {
        int c = ks * 8 + lc;
        qr[ks * 4 + 0] = __float_as_uint(qB[(size_t)qrow0 * H_DIM + c]);
        qr[ks * 4 + 1] = __float_as_uint(qB[(size_t)(qrow0 + 8) * H_DIM + c]);
        qr[ks * 4 + 2] = __float_as_uint(qB[(size_t)qrow0 * H_DIM + c + 4]);
        qr[ks * 4 + 3] = __float_as_uint(qB[(size_t)(qrow0 + 8) * H_DIM + c + 4]);
    }

    float acc[16][4];
#pragma unroll
    for (int nt = 0; nt < 16; nt++)
#pragma unroll
        for (int j = 0; j < 4; j++) acc[nt][j] = 0.f;
    float mrow[2] = {-INFINITY, -INFINITY};
    float lrow[2] = {0.f, 0.f};

    // prologue: stage K(0), V(0) as separate commit groups
    loadK(0);
    loadV(0);

    for (int kv = 0; kv <= qb; kv++) {
        // entry invariant: outstanding groups = [K(kv), V(kv)]
        CP_WAIT1;                 // K(kv) done; V(kv) may still be in flight
        __syncthreads();          // (A) Ks visible

        // ---- S = q @ k^T (1xTF32): 16 rows x 64 kv cols per warp ----
        float sc[8][4];
#pragma unroll
        for (int nt = 0; nt < 8; nt++)
#pragma unroll
            for (int j = 0; j < 4; j++) sc[nt][j] = 0.f;

#pragma unroll
        for (int ks = 0; ks < 16; ks++) {
#pragma unroll
            for (int nt = 0; nt < 8; nt++) {
                uint32_t bh[2];
                bh[0] = __float_as_uint(Ks[(nt * 8 + lr) * AKS + ks * 8 + lc]);
                bh[1] = __float_as_uint(Ks[(nt * 8 + lr) * AKS + ks * 8 + lc + 4]);
                mma_tf32(sc[nt], &qr[ks * 4], bh);
            }
        }
        __syncthreads();          // (B) all warps done reading Ks

        if (kv < qb) loadK(kv + 1);   // lands under softmax + PV

        // Diagonal-block causal mask
        if (kv == qb) {
#pragma unroll
            for (int nt = 0; nt < 8; nt++)
#pragma unroll
                for (int j = 0; j < 4; j++) {
                    int col = nt * 8 + lc * 2 + (j & 1);
                    int row = warp * 16 + lr + (j >> 1) * 8;
                    if (col > row) sc[nt][j] = -INFINITY;
                }
        }

        // ---- warp-local online softmax (exp2 domain) ----
        float mnew[2] = {-INFINITY, -INFINITY};
#pragma unroll
        for (int nt = 0; nt < 8; nt++)
#pragma unroll
            for (int j = 0; j < 4; j++) mnew[j >> 1] = fmaxf(mnew[j >> 1], sc[nt][j]);
#pragma unroll
        for (int off = 1; off < 4; off <<= 1) {
            mnew[0] = fmaxf(mnew[0], __shfl_xor_sync(0xffffffffu, mnew[0], off));
            mnew[1] = fmaxf(mnew[1], __shfl_xor_sync(0xffffffffu, mnew[1], off));
        }
        float mtot0 = fmaxf(mrow[0], mnew[0]);
        float mtot1 = fmaxf(mrow[1], mnew[1]);
        float alpha0 = exp2f(mrow[0] - mtot0);
        float alpha1 = exp2f(mrow[1] - mtot1);
        mrow[0] = mtot0; mrow[1] = mtot1;

        float rs[2] = {0.f, 0.f};
#pragma unroll
        for (int nt = 0; nt < 8; nt++)
#pragma unroll
            for (int j = 0; j < 4; j++) {
                float p = exp2f(sc[nt][j] - ((j >> 1) ? mtot1 : mtot0));
                sc[nt][j] = p;
                rs[j >> 1] += p;
            }
#pragma unroll
        for (int off = 1; off < 4; off <<= 1) {
            rs[0] += __shfl_xor_sync(0xffffffffu, rs[0], off);
            rs[1] += __shfl_xor_sync(0xffffffffu, rs[1], off);
        }
        lrow[0] = lrow[0] * alpha0 + rs[0];
        lrow[1] = lrow[1] * alpha1 + rs[1];

#pragma unroll
        for (int nt = 0; nt < 16; nt++) {
            acc[nt][0] *= alpha0; acc[nt][1] *= alpha0;
            acc[nt][2] *= alpha1; acc[nt][3] *= alpha1;
        }

        // P -> private smem (rna)
        float* Pw = Ps + warp * 16 * APS;
#pragma unroll
        for (int nt = 0; nt < 8; nt++)
#pragma unroll
            for (int j = 0; j < 4; j++) {
                int row = lr + (j >> 1) * 8;
                int col = nt * 8 + lc * 2 + (j & 1);
                Pw[row * APS + col] = __uint_as_float(to_tf32(sc[nt][j]));
            }
        __syncwarp();

        // V(kv) must be complete before PV.
        if (kv < qb) CP_WAIT1; else CP_WAIT0;
        __syncthreads();          // (C) Vs visible

        // ---- O += P @ V (1xTF32): 16 rows x 128 head cols per warp ----
#pragma unroll
        for (int ks2 = 0; ks2 < 8; ks2++) {
            uint32_t pa[4];
            pa[0] = __float_as_uint(Pw[lr * APS + ks2 * 8 + lc]);
            pa[1] = __float_as_uint(Pw[(lr + 8) * APS + ks2 * 8 + lc]);
            pa[2] = __float_as_uint(Pw[lr * APS + ks2 * 8 + lc + 4]);
            pa[3] = __float_as_uint(Pw[(lr + 8) * APS + ks2 * 8 + lc + 4]);
#pragma unroll
            for (int nt2 = 0; nt2 < 16; nt2++) {
                uint32_t vb[2];
                vb[0] = __float_as_uint(Vs[(ks2 * 8 + lc) * AVS + nt2 * 8 + lr]);
                vb[1] = __float_as_uint(Vs[(ks2 * 8 + lc + 4) * AVS + nt2 * 8 + lr]);
                mma_tf32(acc[nt2], pa, vb);
            }
        }
        __syncthreads();          // (D) all warps done reading Vs

        if (kv < qb) loadV(kv + 1);   // lands under QK of next tile
    }

    // Epilogue
    float inv0 = 1.f / lrow[0];
    float inv1 = 1.f / lrow[1];
    size_t obase = ((size_t)b * S_LEN + qrow0) * H_DIM;
#pragma unroll
    for (int nt2 = 0; nt2 < 16; nt2++) {
        int col = nt2 * 8 + lc * 2;
        *(float2*)(out + obase + col) =
            make_float2(acc[nt2][0] * inv0, acc[nt2][1] * inv0);
        *(float2*)(out + obase + (size_t)8 * H_DIM + col) =
            make_float2(acc[nt2][2] * inv1, acc[nt2][3] * inv1);
    }
}

// ---------------- launch ----------------

extern "C" void kernel_launch(void* const* d_in, const int* in_sizes, int n_in,
                              void* d_out, int out_size) {
    const float* x     = (const float*)d_in[0];
    const float* w_dkv = (const float*)d_in[1];
    const float* w_k   = (const float*)d_in[2];
    const float* w_v   = (const float*)d_in[3];
    const float* w_q   = (const float*)d_in[4];

    float* out = (float*)d_out;                          // [B,S,HEAD]
    float* latent = out + (size_t)M_TOTAL * H_DIM;       // [B,S,LATENT]

    float *qp, *kp, *vp, *wr;
    cudaGetSymbolAddress((void**)&qp, g_q);
    cudaGetSymbolAddress((void**)&kp, g_k);
    cudaGetSymbolAddress((void**)&vp, g_v);
    cudaGetSymbolAddress((void**)&wr, g_wr);

    static bool attrs_set = false;
    if (!attrs_set) {
        cudaFuncSetAttribute(gemm1_fused,
                             cudaFuncAttributeMaxDynamicSharedMemorySize, G_SMEM);
        cudaFuncSetAttribute(attn_kernel,
                             cudaFuncAttributeMaxDynamicSharedMemorySize, ATTN_SMEM_BYTES);
        attrs_set = true;
    }

    // 0) pre-round all weights to tf32-rna (unbiased)
    prep_w<<<WR_TOT / 256, 256>>>(w_dkv, w_q, w_k, w_v);

    // 1) fused: latent -> d_out; q (rna), k (scaled, rna), v (rna) -> scratch
    gemm1_fused<<<M_TOTAL / 64, 256, G_SMEM>>>(x, wr, latent, qp, kp, vp);

    // 2) causal flash attention (512 CTAs x 128 thr, 2/SM, longest-first)
    attn_kernel<<<512, 128, ATTN_SMEM_BYTES>>>(qp, kp, vp, out);
}